// round 14
// baseline (speedup 1.0000x reference)
#include <cuda_runtime.h>
#include <cuda_fp16.h>
#include <math.h>
#include <stdint.h>

// Problem dims (fixed)
#define NB 8
#define NT 4096
#define ND 768
#define NH 12
#define NK 64
#define NM (NB*NT)          // 32768 rows
#define CC 64               // chunks along T (wkv scan)
#define LL 64               // chunk length

// GEMM tiling: BM=BN=128, 256 threads, 2 CTAs/SM, GBK=96, fp16, 2-stage
#define BM 128
#define BN 128
#define GBK 96
#define NCH (ND/GBK)        // 8 k-iterations
#define GRS 104             // smem row stride in fp16 elems (208B, conflict-free)
#define SUBB (128*GRS*2)    // bytes per subtile (26624)
#define OAH 0
#define OBH SUBB
#define STGB (2*SUBB)       // 53248 B per stage
#define GEMM_SMEM_BYTES (2*STGB)    // 106496 B (2 CTAs/SM: 212992 < 228KB)
#define CHK_PER_SUB (128*(GBK/8))   // 1536 16B-chunks per subtile

// ---------------------------------------------------------------------------
// Scratch buffers (all intermediates fp16)
// ---------------------------------------------------------------------------
__device__ __half g_xrh[(size_t)NM * ND];   // xr -> (after norm) yn
__device__ __half g_xkh[(size_t)NM * ND];   // xk
__device__ __half g_xvh[(size_t)NM * ND];   // xv
__device__ __half g_k16[(size_t)NM * ND];   // k
__device__ __half g_v16[(size_t)NM * ND];   // v
__device__ __half g_r16[(size_t)NM * ND];   // r
__device__ __half g_y16[(size_t)NM * ND];   // y (pre-norm)
__device__ __half g_Wh[4][ND * ND];         // fp16 weights

// wkv chunked-scan intermediates
__device__ float g_Nloc[NB * NH * CC * NK];
__device__ float g_Dloc[NB * NH * CC * NK];
__device__ float g_InN [NB * NH * CC * NK];
__device__ float g_InD [NB * NH * CC * NK];
__device__ float g_s1[NB * NH];
__device__ float g_s2[NB * NH];

// ---------------------------------------------------------------------------
// helpers
// ---------------------------------------------------------------------------
__device__ __forceinline__ uint32_t smem_u32(const void* p) {
    uint32_t a;
    asm("{ .reg .u64 t; cvta.to.shared.u64 t, %1; cvt.u32.u64 %0, t; }"
        : "=r"(a) : "l"(p));
    return a;
}

__device__ __forceinline__ uint32_t packh(float a, float b) {
    uint32_t r;
    asm("cvt.rn.f16x2.f32 %0, %1, %2;" : "=r"(r) : "f"(b), "f"(a));
    return r;
}

__device__ __forceinline__ uint4 pack8h(const float* m) {
    uint4 r;
    r.x = packh(m[0], m[1]);
    r.y = packh(m[2], m[3]);
    r.z = packh(m[4], m[5]);
    r.w = packh(m[6], m[7]);
    return r;
}

__device__ __forceinline__ void ldsm4(uint32_t* r, uint32_t addr) {
    asm volatile("ldmatrix.sync.aligned.m8n8.x4.shared.b16 {%0,%1,%2,%3}, [%4];"
                 : "=r"(r[0]), "=r"(r[1]), "=r"(r[2]), "=r"(r[3]) : "r"(addr));
}

__device__ __forceinline__ void mma16816(float* c, const uint32_t* a, const uint32_t* b) {
    asm volatile(
        "mma.sync.aligned.m16n8k16.row.col.f32.f16.f16.f32 "
        "{%0,%1,%2,%3}, {%4,%5,%6,%7}, {%8,%9}, {%0,%1,%2,%3};"
        : "+f"(c[0]), "+f"(c[1]), "+f"(c[2]), "+f"(c[3])
        : "r"(a[0]), "r"(a[1]), "r"(a[2]), "r"(a[3]), "r"(b[0]), "r"(b[1]));
}

__device__ __forceinline__ void cpasync16(uint32_t saddr, const void* gptr) {
    asm volatile("cp.async.cg.shared.global [%0], [%1], 16;"
                 :: "r"(saddr), "l"(__cvta_generic_to_global(gptr)));
}

// ---------------------------------------------------------------------------
// fused weight convert (grid.y = 4): fp32 W -> fp16
// ---------------------------------------------------------------------------
__global__ void split_all(const float* __restrict__ W0, const float* __restrict__ W1,
                          const float* __restrict__ W2, const float* __restrict__ W3,
                          __half* __restrict__ whbase)
{
    const int z = blockIdx.y;
    const float* src = (z == 0) ? W0 : (z == 1) ? W1 : (z == 2) ? W2 : W3;
    __half* h = whbase + (size_t)z * ND * ND;
    const int n8 = ND * ND / 8;
    int idx = blockIdx.x * blockDim.x + threadIdx.x;
    if (idx >= n8) return;
    const float4* s4 = (const float4*)src;
    float4 a0 = s4[idx*2], a1 = s4[idx*2+1];
    float m[8] = {a0.x,a0.y,a0.z,a0.w,a1.x,a1.y,a1.z,a1.w};
    ((uint4*)h)[idx] = pack8h(m);
}

// ---------------------------------------------------------------------------
// 1) Token-shift mixing, fp16 output
// ---------------------------------------------------------------------------
__global__ void mix_f16(const float* __restrict__ x,
                        const float* __restrict__ tmr,
                        const float* __restrict__ tmk,
                        const float* __restrict__ tmv)
{
    size_t idx = (size_t)blockIdx.x * blockDim.x + threadIdx.x;
    const size_t n8 = (size_t)NM * ND / 8;
    if (idx >= n8) return;
    size_t e = idx * 8;
    int d = (int)(e % ND);
    int t = (int)((e / ND) % NT);

    const float4* x4 = (const float4*)x;
    float4 a0 = x4[idx*2], a1 = x4[idx*2+1];
    float4 p0 = make_float4(0.f,0.f,0.f,0.f), p1 = p0;
    if (t != 0) { p0 = x4[idx*2 - ND/4]; p1 = x4[idx*2 + 1 - ND/4]; }

    float xc[8] = {a0.x,a0.y,a0.z,a0.w,a1.x,a1.y,a1.z,a1.w};
    float xp[8] = {p0.x,p0.y,p0.z,p0.w,p1.x,p1.y,p1.z,p1.w};

    float mr[8], mk[8], mv[8];
    {
        float4 r0 = ((const float4*)tmr)[d>>2], r1 = ((const float4*)tmr)[(d>>2)+1];
        float4 k0 = ((const float4*)tmk)[d>>2], k1 = ((const float4*)tmk)[(d>>2)+1];
        float4 v0 = ((const float4*)tmv)[d>>2], v1 = ((const float4*)tmv)[(d>>2)+1];
        float mrr[8] = {r0.x,r0.y,r0.z,r0.w,r1.x,r1.y,r1.z,r1.w};
        float mkk[8] = {k0.x,k0.y,k0.z,k0.w,k1.x,k1.y,k1.z,k1.w};
        float mvv[8] = {v0.x,v0.y,v0.z,v0.w,v1.x,v1.y,v1.z,v1.w};
#pragma unroll
        for (int i = 0; i < 8; i++) {
            float dx = xc[i] - xp[i];
            mr[i] = fmaf(dx, mrr[i], xp[i]);
            mk[i] = fmaf(dx, mkk[i], xp[i]);
            mv[i] = fmaf(dx, mvv[i], xp[i]);
        }
    }
    ((uint4*)g_xrh)[idx] = pack8h(mr);
    ((uint4*)g_xkh)[idx] = pack8h(mk);
    ((uint4*)g_xvh)[idx] = pack8h(mv);
}

// ---------------------------------------------------------------------------
// 2) Batched tensor-core GEMM, pure fp16: C = A*Wh  (2-stage, 2 CTAs/SM, GBK=96)
// ---------------------------------------------------------------------------
struct GemmArgs {
    const __half* A[3];
    const __half* B[3];
    void* C[3];
    int actmask;   // bit z: apply sigmoid
    int f16mask;   // bit z: output fp16
};

__global__ void __launch_bounds__(256, 2)
gemm_mma_batched(GemmArgs args)
{
    extern __shared__ __half smraw[];
    const uint32_t sb = smem_u32(smraw);
    const int tid  = threadIdx.x;
    const int lane = tid & 31;
    const int wid  = tid >> 5;
    const int z  = blockIdx.z;
    const int m0 = blockIdx.y * BM;
    const int n0 = blockIdx.x * BN;
    const int wm = (wid >> 2) * 64;
    const int wn = (wid & 3) * 32;

    const __half* __restrict__ A = args.A[z];
    const __half* __restrict__ B = args.B[z];
    const bool act = (args.actmask >> z) & 1;
    const bool o16 = (args.f16mask >> z) & 1;

    float acc[4][4][4];
#pragma unroll
    for (int i = 0; i < 4; i++)
#pragma unroll
        for (int j = 0; j < 4; j++)
#pragma unroll
            for (int q = 0; q < 4; q++) acc[i][j][q] = 0.f;

    // ---- stage loader: 1536 16B-chunks per subtile, 6 per thread each ----
    auto do_issue = [&](int it, int stg) {
        const int kt = it * GBK;
        const uint32_t sbase = sb + (uint32_t)stg * STGB;
#pragma unroll
        for (int j = 0; j < CHK_PER_SUB / 256; j++) {     // 6
            int g   = tid + j * 256;        // 0..1535
            int row = g / (GBK / 8);        // /12 -> 0..127
            int kc  = (g % (GBK / 8)) * 8;  // 0..88
            uint32_t so = (uint32_t)(row * GRS + kc) * 2;
            size_t ga = (size_t)(m0 + row) * ND + kt + kc;
            size_t gb = (size_t)(n0 + row) * ND + kt + kc;
            cpasync16(sbase + OAH + so, A + ga);
            cpasync16(sbase + OBH + so, B + gb);
        }
        asm volatile("cp.async.commit_group;");
    };

    // ---- compute one stage: 6 x k16 steps ----
    auto do_compute = [&](int stg) {
        const uint32_t base = sb + (uint32_t)stg * STGB;
        const int arow = wm + (lane & 15);
        const int acol0 = (lane >> 4) * 8;
        const int brow = wn + ((lane >> 4) << 3) + (lane & 7);
        const int bcol0 = ((lane >> 3) & 1) * 8;
#pragma unroll
        for (int ks = 0; ks < GBK / 16; ks++) {           // 6
            uint32_t ah[4][4], bh[4][2];
            const int kofs = ks * 16;
#pragma unroll
            for (int mi = 0; mi < 4; mi++) {
                uint32_t ad = base + OAH
                            + (uint32_t)((arow + mi * 16) * GRS + kofs + acol0) * 2;
                ldsm4(ah[mi], ad);
            }
#pragma unroll
            for (int nj = 0; nj < 2; nj++) {
                uint32_t bd = base + OBH
                            + (uint32_t)((brow + nj * 16) * GRS + kofs + bcol0) * 2;
                uint32_t t[4];
                ldsm4(t, bd);
                bh[nj*2][0] = t[0]; bh[nj*2][1] = t[1];
                bh[nj*2+1][0] = t[2]; bh[nj*2+1][1] = t[3];
            }
#pragma unroll
            for (int mi = 0; mi < 4; mi++)
#pragma unroll
                for (int ni = 0; ni < 4; ni++)
                    mma16816(acc[mi][ni], ah[mi], bh[ni]);
        }
    };

    do_issue(0, 0);
    for (int it = 0; it < NCH; it++) {
        asm volatile("cp.async.wait_group 0;");
        __syncthreads();
        if (it + 1 < NCH) do_issue(it + 1, (it + 1) & 1);
        do_compute(it & 1);
    }

    // ---- epilogue ----
#pragma unroll
    for (int mi = 0; mi < 4; mi++) {
        int row = m0 + wm + mi * 16 + (lane >> 2);
#pragma unroll
        for (int ni = 0; ni < 4; ni++) {
            int col = n0 + wn + ni * 8 + (lane & 3) * 2;
            float c0 = acc[mi][ni][0], c1 = acc[mi][ni][1];
            float c2 = acc[mi][ni][2], c3 = acc[mi][ni][3];
            if (act) {
                c0 = 1.f / (1.f + __expf(-c0));
                c1 = 1.f / (1.f + __expf(-c1));
                c2 = 1.f / (1.f + __expf(-c2));
                c3 = 1.f / (1.f + __expf(-c3));
            }
            if (o16) {
                __half* Ch = (__half*)args.C[z];
                *(uint32_t*)(Ch + (size_t)row * ND + col)       = packh(c0, c1);
                *(uint32_t*)(Ch + (size_t)(row + 8) * ND + col) = packh(c2, c3);
            } else {
                float* Cf = (float*)args.C[z];
                *(float2*)(Cf + (size_t)row * ND + col)       = make_float2(c0, c1);
                *(float2*)(Cf + (size_t)(row + 8) * ND + col) = make_float2(c2, c3);
            }
        }
    }
}

// ---------------------------------------------------------------------------
// 3a) WKV chunk aggregates — 128 threads = 4 warps, one chunk per warp
// ---------------------------------------------------------------------------
__global__ void __launch_bounds__(128)
wkv_chunk_agg(const __half* __restrict__ kArr,
              const __half* __restrict__ vArr,
              const float* __restrict__ td)
{
    const int bh = blockIdx.x;
    const int c  = blockIdx.y * 4 + (threadIdx.x >> 5);
    const int b = bh / NH;
    const int h = bh - b * NH;
    const int kk = threadIdx.x & 31;
    const int ch = h * NK + 2 * kk;

    const float w0 = __expf(-__expf(td[ch]));
    const float w1 = __expf(-__expf(td[ch + 1]));
    size_t base2 = ((size_t)b * NT * ND + (size_t)c * LL * ND + ch) >> 1;
    const __half2* k2 = (const __half2*)kArr;
    const __half2* v2 = (const __half2*)vArr;

    float N0 = 0.f, N1 = 0.f, D0 = 0.f, D1 = 0.f;
#pragma unroll 8
    for (int i = 0; i < LL; i++) {
        size_t idx = base2 + (size_t)i * (ND / 2);
        float2 kf = __half22float2(k2[idx]);
        float2 vf = __half22float2(v2[idx]);
        float e0 = __expf(kf.x), e1 = __expf(kf.y);
        N0 = fmaf(N0, w0, e0 * vf.x);
        D0 = fmaf(D0, w0, e0);
        N1 = fmaf(N1, w1, e1 * vf.y);
        D1 = fmaf(D1, w1, e1);
    }
    int o = (bh * CC + c) * NK + 2 * kk;
    g_Nloc[o]     = N0;  g_Nloc[o + 1] = N1;
    g_Dloc[o]     = D0;  g_Dloc[o + 1] = D1;
}

// ---------------------------------------------------------------------------
// 3b) scan across chunks
// ---------------------------------------------------------------------------
__global__ void __launch_bounds__(64)
wkv_chunk_scan(const float* __restrict__ td)
{
    const int bh = blockIdx.x;
    const int b = bh / NH;
    const int h = bh - b * NH;
    const int kk = threadIdx.x;
    const int ch = h * NK + kk;

    if (kk == 0) { g_s1[bh] = 0.f; g_s2[bh] = 0.f; }

    const float wL = __expf(-(float)LL * __expf(td[ch]));

    float cN = 0.f, cD = 0.f;
    for (int c = 0; c < CC; c++) {
        int o = (bh * CC + c) * NK + kk;
        g_InN[o] = cN;
        g_InD[o] = cD;
        cN = fmaf(cN, wL, g_Nloc[o]);
        cD = fmaf(cD, wL, g_Dloc[o]);
    }
}

// ---------------------------------------------------------------------------
// 3c) WKV outputs — 128 threads = 4 warps, one chunk per warp + GN sums
// ---------------------------------------------------------------------------
__global__ void __launch_bounds__(128)
wkv_out(const __half* __restrict__ kArr,
        const __half* __restrict__ vArr,
        const __half* __restrict__ rArr,
        const float* __restrict__ td,
        const float* __restrict__ tf,
        __half* __restrict__ y)
{
    const int bh = blockIdx.x;
    const int c  = blockIdx.y * 4 + (threadIdx.x >> 5);
    const int b = bh / NH;
    const int h = bh - b * NH;
    const int kk = threadIdx.x & 31;
    const int ch = h * NK + 2 * kk;

    const float w0  = __expf(-__expf(td[ch]));
    const float w1  = __expf(-__expf(td[ch + 1]));
    const float eu0 = __expf(tf[ch]);
    const float eu1 = __expf(tf[ch + 1]);
    size_t base2 = ((size_t)b * NT * ND + (size_t)c * LL * ND + ch) >> 1;
    const __half2* k2 = (const __half2*)kArr;
    const __half2* v2 = (const __half2*)vArr;
    const __half2* r2 = (const __half2*)rArr;
    __half2* y2 = (__half2*)y;

    int o = (bh * CC + c) * NK + 2 * kk;
    float num0 = g_InN[o], num1 = g_InN[o + 1];
    float den0 = g_InD[o], den1 = g_InD[o + 1];

    float s1 = 0.f, s2 = 0.f;
#pragma unroll 4
    for (int i = 0; i < LL; i++) {
        size_t idx = base2 + (size_t)i * (ND / 2);
        float2 kf = __half22float2(k2[idx]);
        float2 vf = __half22float2(v2[idx]);
        float2 rf = __half22float2(r2[idx]);
        float e0 = __expf(kf.x), e1 = __expf(kf.y);
        float ekv0 = e0 * vf.x, ekv1 = e1 * vf.y;
        float yy0 = rf.x * __fdividef(fmaf(eu0, ekv0, num0),
                                      fmaf(eu0, e0, den0) + 1e-9f);
        float yy1 = rf.y * __fdividef(fmaf(eu1, ekv1, num1),
                                      fmaf(eu1, e1, den1) + 1e-9f);
        y2[idx] = __floats2half2_rn(yy0, yy1);
        s1 += yy0 + yy1;
        s2 = fmaf(yy0, yy0, s2);
        s2 = fmaf(yy1, yy1, s2);
        num0 = fmaf(num0, w0, ekv0);
        den0 = fmaf(den0, w0, e0);
        num1 = fmaf(num1, w1, ekv1);
        den1 = fmaf(den1, w1, e1);
    }

#pragma unroll
    for (int off = 16; off > 0; off >>= 1) {
        s1 += __shfl_down_sync(0xffffffffu, s1, off);
        s2 += __shfl_down_sync(0xffffffffu, s2, off);
    }
    if (kk == 0) {
        atomicAdd(&g_s1[bh], s1);
        atomicAdd(&g_s2[bh], s2);
    }
}

// ---------------------------------------------------------------------------
// 4) GroupNorm apply: fp16 y in -> fp16 yn out (into g_xrh)
// ---------------------------------------------------------------------------
__global__ void norm_f16(const float* __restrict__ gnw,
                         const float* __restrict__ gnb)
{
    size_t idx = (size_t)blockIdx.x * blockDim.x + threadIdx.x;
    const size_t n8 = (size_t)NM * ND / 8;
    if (idx >= n8) return;
    size_t e = idx * 8;
    int d = (int)(e % ND);
    int b = (int)(e / ((size_t)NT * ND));
    int h = d >> 6;
    int bh = b * NH + h;

    const float inv = 1.f / (float)(NT * NK);
    float mean = g_s1[bh] * inv;
    float var  = g_s2[bh] * inv - mean * mean;
    float rstd = rsqrtf(var + 1e-5f);

    uint4 raw = ((const uint4*)g_y16)[idx];
    float yv[8];
    {
        __half2 p0 = *(__half2*)&raw.x;
        __half2 p1 = *(__half2*)&raw.y;
        __half2 p2 = *(__half2*)&raw.z;
        __half2 p3 = *(__half2*)&raw.w;
        float2 f0 = __half22float2(p0), f1 = __half22float2(p1);
        float2 f2 = __half22float2(p2), f3 = __half22float2(p3);
        yv[0]=f0.x; yv[1]=f0.y; yv[2]=f1.x; yv[3]=f1.y;
        yv[4]=f2.x; yv[5]=f2.y; yv[6]=f3.x; yv[7]=f3.y;
    }
    float4 w0 = ((const float4*)gnw)[d>>2], w1 = ((const float4*)gnw)[(d>>2)+1];
    float4 b0 = ((const float4*)gnb)[d>>2], b1 = ((const float4*)gnb)[(d>>2)+1];
    float wv[8] = {w0.x,w0.y,w0.z,w0.w,w1.x,w1.y,w1.z,w1.w};
    float bv[8] = {b0.x,b0.y,b0.z,b0.w,b1.x,b1.y,b1.z,b1.w};
    float m[8];
#pragma unroll
    for (int i = 0; i < 8; i++)
        m[i] = (yv[i] - mean) * rstd * wv[i] + bv[i];

    ((uint4*)g_xrh)[idx] = pack8h(m);
}

// ---------------------------------------------------------------------------
// host launcher — single-stream, proven-best schedule
// ---------------------------------------------------------------------------
extern "C" void kernel_launch(void* const* d_in, const int* in_sizes, int n_in,
                              void* d_out, int out_size)
{
    const float* x   = (const float*)d_in[0];
    const float* tmr = (const float*)d_in[1];
    const float* tmk = (const float*)d_in[2];
    const float* tmv = (const float*)d_in[3];
    const float* td  = (const float*)d_in[4];
    const float* tf  = (const float*)d_in[5];
    const float* Wr  = (const float*)d_in[6];
    const float* Wk  = (const float*)d_in[7];
    const float* Wv  = (const float*)d_in[8];
    const float* Wo  = (const float*)d_in[9];
    const float* gnw = (const float*)d_in[10];
    const float* gnb = (const float*)d_in[11];
    float* out = (float*)d_out;

    __half *xrh, *xkh, *xvh, *k16, *v16, *r16, *y16, *wh;
    cudaGetSymbolAddress((void**)&xrh, g_xrh);
    cudaGetSymbolAddress((void**)&xkh, g_xkh);
    cudaGetSymbolAddress((void**)&xvh, g_xvh);
    cudaGetSymbolAddress((void**)&k16, g_k16);
    cudaGetSymbolAddress((void**)&v16, g_v16);
    cudaGetSymbolAddress((void**)&r16, g_r16);
    cudaGetSymbolAddress((void**)&y16, g_y16);
    cudaGetSymbolAddress((void**)&wh, g_Wh);

    cudaFuncSetAttribute((const void*)gemm_mma_batched,
                         cudaFuncAttributeMaxDynamicSharedMemorySize,
                         GEMM_SMEM_BYTES);

    const size_t n8 = (size_t)NM * ND / 8;
    const int blk = 256;
    const int grd8 = (int)((n8 + blk - 1) / blk);
    const int wn8 = ND * ND / 8;
    const int wgrd = (wn8 + blk - 1) / blk;

    // weight converts + mix
    dim3 sgrid(wgrd, 4);
    split_all<<<sgrid, blk>>>(Wr, Wk, Wv, Wo, wh);
    mix_f16<<<grd8, blk>>>(x, tmr, tmk, tmv);

    // fused r/k/v projections (single batched launch)
    GemmArgs qkv;
    qkv.A[0] = xrh; qkv.B[0] = wh + 0*(size_t)ND*ND; qkv.C[0] = r16;  // r (sigmoid)
    qkv.A[1] = xkh; qkv.B[1] = wh + 1*(size_t)ND*ND; qkv.C[1] = k16;  // k
    qkv.A[2] = xvh; qkv.B[2] = wh + 2*(size_t)ND*ND; qkv.C[2] = v16;  // v
    qkv.actmask = 1;
    qkv.f16mask = 7;
    dim3 ggrid(ND / BN, NM / BM, 3);   // (6, 256, 3)
    gemm_mma_batched<<<ggrid, 256, GEMM_SMEM_BYTES>>>(qkv);

    // chunked parallel WKV scan: y -> y16
    dim3 wgrid(NB * NH, CC / 4);
    wkv_chunk_agg <<<wgrid, 128>>>(k16, v16, td);
    wkv_chunk_scan<<<NB * NH, 64>>>(td);
    wkv_out       <<<wgrid, 128>>>(k16, v16, r16, td, tf, y16);

    // GroupNorm apply -> fp16 yn (into xrh)
    norm_f16<<<grd8, blk>>>(gnw, gnb);

    // output projection (fp32 into d_out)
    GemmArgs og;
    og.A[0] = xrh; og.B[0] = wh + 3*(size_t)ND*ND; og.C[0] = out;
    og.A[1] = og.A[2] = xrh;
    og.B[1] = og.B[2] = og.B[0];
    og.C[1] = og.C[2] = out;
    og.actmask = 0;
    og.f16mask = 0;
    dim3 ogrid(ND / BN, NM / BM, 1);
    gemm_mma_batched<<<ogrid, 256, GEMM_SMEM_BYTES>>>(og);
}

// round 15
// speedup vs baseline: 1.0938x; 1.0938x over previous
#include <cuda_runtime.h>
#include <cuda_fp16.h>
#include <math.h>
#include <stdint.h>

// Problem dims (fixed)
#define NB 8
#define NT 4096
#define ND 768
#define NH 12
#define NK 64
#define NM (NB*NT)          // 32768 rows
#define CC 64               // chunks along T (wkv scan)
#define LL 64               // chunk length

// GEMM tiling: BM=BN=128, 256 threads, 2 CTAs/SM, GBK=64, fp16, 2-stage
// (empirically optimal across rounds 9-14; do not disturb)
#define BM 128
#define BN 128
#define GBK 64
#define NCH (ND/GBK)        // 12 k-iterations
#define GRS 72              // smem row stride in fp16 elems (144B)
#define SUBB (128*GRS*2)    // bytes per subtile (18432)
#define OAH 0
#define OBH SUBB
#define STGB (2*SUBB)       // 36864 B per stage
#define GEMM_SMEM_BYTES (2*STGB)    // 73728 B

// ---------------------------------------------------------------------------
// Scratch buffers (all intermediates fp16)
// ---------------------------------------------------------------------------
__device__ __half g_xrh[(size_t)NM * ND];   // xr -> (after norm) yn
__device__ __half g_xkh[(size_t)NM * ND];   // xk
__device__ __half g_xvh[(size_t)NM * ND];   // xv
__device__ __half g_k16[(size_t)NM * ND];   // k
__device__ __half g_v16[(size_t)NM * ND];   // v
__device__ __half g_r16[(size_t)NM * ND];   // r
__device__ __half g_y16[(size_t)NM * ND];   // y (pre-norm)
__device__ __half g_Wh[4][ND * ND];         // fp16 weights

// wkv chunked-scan intermediates
__device__ float g_Nloc[NB * NH * CC * NK];
__device__ float g_Dloc[NB * NH * CC * NK];
__device__ float g_InN [NB * NH * CC * NK];
__device__ float g_InD [NB * NH * CC * NK];
__device__ float g_s1[NB * NH];
__device__ float g_s2[NB * NH];

// ---------------------------------------------------------------------------
// helpers
// ---------------------------------------------------------------------------
__device__ __forceinline__ uint32_t smem_u32(const void* p) {
    uint32_t a;
    asm("{ .reg .u64 t; cvta.to.shared.u64 t, %1; cvt.u32.u64 %0, t; }"
        : "=r"(a) : "l"(p));
    return a;
}

__device__ __forceinline__ uint32_t packh(float a, float b) {
    uint32_t r;
    asm("cvt.rn.f16x2.f32 %0, %1, %2;" : "=r"(r) : "f"(b), "f"(a));
    return r;
}

__device__ __forceinline__ uint4 pack8h(const float* m) {
    uint4 r;
    r.x = packh(m[0], m[1]);
    r.y = packh(m[2], m[3]);
    r.z = packh(m[4], m[5]);
    r.w = packh(m[6], m[7]);
    return r;
}

__device__ __forceinline__ void ldsm4(uint32_t* r, uint32_t addr) {
    asm volatile("ldmatrix.sync.aligned.m8n8.x4.shared.b16 {%0,%1,%2,%3}, [%4];"
                 : "=r"(r[0]), "=r"(r[1]), "=r"(r[2]), "=r"(r[3]) : "r"(addr));
}

__device__ __forceinline__ void mma16816(float* c, const uint32_t* a, const uint32_t* b) {
    asm volatile(
        "mma.sync.aligned.m16n8k16.row.col.f32.f16.f16.f32 "
        "{%0,%1,%2,%3}, {%4,%5,%6,%7}, {%8,%9}, {%0,%1,%2,%3};"
        : "+f"(c[0]), "+f"(c[1]), "+f"(c[2]), "+f"(c[3])
        : "r"(a[0]), "r"(a[1]), "r"(a[2]), "r"(a[3]), "r"(b[0]), "r"(b[1]));
}

__device__ __forceinline__ void cpasync16(uint32_t saddr, const void* gptr) {
    asm volatile("cp.async.cg.shared.global [%0], [%1], 16;"
                 :: "r"(saddr), "l"(__cvta_generic_to_global(gptr)));
}

// ---------------------------------------------------------------------------
// 1) Fused prep: blockIdx.y 0..3 -> weight converts, 4 -> token-shift mix
// ---------------------------------------------------------------------------
__global__ void prep_all(const float* __restrict__ x,
                         const float* __restrict__ tmr,
                         const float* __restrict__ tmk,
                         const float* __restrict__ tmv,
                         const float* __restrict__ W0, const float* __restrict__ W1,
                         const float* __restrict__ W2, const float* __restrict__ W3,
                         __half* __restrict__ whbase)
{
    const int z = blockIdx.y;
    if (z < 4) {
        const int n8 = ND * ND / 8;
        int idx = blockIdx.x * blockDim.x + threadIdx.x;
        if (idx >= n8) return;
        const float* src = (z == 0) ? W0 : (z == 1) ? W1 : (z == 2) ? W2 : W3;
        __half* h = whbase + (size_t)z * ND * ND;
        const float4* s4 = (const float4*)src;
        float4 a0 = s4[idx*2], a1 = s4[idx*2+1];
        float m[8] = {a0.x,a0.y,a0.z,a0.w,a1.x,a1.y,a1.z,a1.w};
        ((uint4*)h)[idx] = pack8h(m);
        return;
    }

    // mix path
    size_t idx = (size_t)blockIdx.x * blockDim.x + threadIdx.x;
    const size_t n8 = (size_t)NM * ND / 8;
    if (idx >= n8) return;
    size_t e = idx * 8;
    int d = (int)(e % ND);
    int t = (int)((e / ND) % NT);

    const float4* x4 = (const float4*)x;
    float4 a0 = x4[idx*2], a1 = x4[idx*2+1];
    float4 p0 = make_float4(0.f,0.f,0.f,0.f), p1 = p0;
    if (t != 0) { p0 = x4[idx*2 - ND/4]; p1 = x4[idx*2 + 1 - ND/4]; }

    float xc[8] = {a0.x,a0.y,a0.z,a0.w,a1.x,a1.y,a1.z,a1.w};
    float xp[8] = {p0.x,p0.y,p0.z,p0.w,p1.x,p1.y,p1.z,p1.w};

    float mr[8], mk[8], mv[8];
    {
        float4 r0 = ((const float4*)tmr)[d>>2], r1 = ((const float4*)tmr)[(d>>2)+1];
        float4 k0 = ((const float4*)tmk)[d>>2], k1 = ((const float4*)tmk)[(d>>2)+1];
        float4 v0 = ((const float4*)tmv)[d>>2], v1 = ((const float4*)tmv)[(d>>2)+1];
        float mrr[8] = {r0.x,r0.y,r0.z,r0.w,r1.x,r1.y,r1.z,r1.w};
        float mkk[8] = {k0.x,k0.y,k0.z,k0.w,k1.x,k1.y,k1.z,k1.w};
        float mvv[8] = {v0.x,v0.y,v0.z,v0.w,v1.x,v1.y,v1.z,v1.w};
#pragma unroll
        for (int i = 0; i < 8; i++) {
            float dx = xc[i] - xp[i];
            mr[i] = fmaf(dx, mrr[i], xp[i]);
            mk[i] = fmaf(dx, mkk[i], xp[i]);
            mv[i] = fmaf(dx, mvv[i], xp[i]);
        }
    }
    ((uint4*)g_xrh)[idx] = pack8h(mr);
    ((uint4*)g_xkh)[idx] = pack8h(mk);
    ((uint4*)g_xvh)[idx] = pack8h(mv);
}

// ---------------------------------------------------------------------------
// 2) Batched tensor-core GEMM, pure fp16: C = A*Wh  (2-stage, 2 CTAs/SM)
// ---------------------------------------------------------------------------
struct GemmArgs {
    const __half* A[3];
    const __half* B[3];
    void* C[3];
    int actmask;   // bit z: apply sigmoid
    int f16mask;   // bit z: output fp16
};

__global__ void __launch_bounds__(256, 2)
gemm_mma_batched(GemmArgs args)
{
    extern __shared__ __half smraw[];
    const uint32_t sb = smem_u32(smraw);
    const int tid  = threadIdx.x;
    const int lane = tid & 31;
    const int wid  = tid >> 5;
    const int z  = blockIdx.z;
    const int m0 = blockIdx.y * BM;
    const int n0 = blockIdx.x * BN;
    const int wm = (wid >> 2) * 64;
    const int wn = (wid & 3) * 32;

    const __half* __restrict__ A = args.A[z];
    const __half* __restrict__ B = args.B[z];
    const bool act = (args.actmask >> z) & 1;
    const bool o16 = (args.f16mask >> z) & 1;

    float acc[4][4][4];
#pragma unroll
    for (int i = 0; i < 4; i++)
#pragma unroll
        for (int j = 0; j < 4; j++)
#pragma unroll
            for (int q = 0; q < 4; q++) acc[i][j][q] = 0.f;

    auto do_issue = [&](int it, int stg) {
        const int kt = it * GBK;
        const uint32_t sbase = sb + (uint32_t)stg * STGB;
#pragma unroll
        for (int j = 0; j < 4; j++) {
            int g   = tid + j * 256;       // 0..1023
            int row = g >> 3;              // 0..127
            int kc  = (g & 7) * 8;         // 0..56
            uint32_t so = (uint32_t)(row * GRS + kc) * 2;
            size_t ga = (size_t)(m0 + row) * ND + kt + kc;
            size_t gb = (size_t)(n0 + row) * ND + kt + kc;
            cpasync16(sbase + OAH + so, A + ga);
            cpasync16(sbase + OBH + so, B + gb);
        }
        asm volatile("cp.async.commit_group;");
    };

    auto do_compute = [&](int stg) {
        const uint32_t base = sb + (uint32_t)stg * STGB;
        const int arow = wm + (lane & 15);
        const int acol0 = (lane >> 4) * 8;
        const int brow = wn + ((lane >> 4) << 3) + (lane & 7);
        const int bcol0 = ((lane >> 3) & 1) * 8;
#pragma unroll
        for (int ks = 0; ks < 4; ks++) {
            uint32_t ah[4][4], bh[4][2];
            const int kofs = ks * 16;
#pragma unroll
            for (int mi = 0; mi < 4; mi++) {
                uint32_t ad = base + OAH
                            + (uint32_t)((arow + mi * 16) * GRS + kofs + acol0) * 2;
                ldsm4(ah[mi], ad);
            }
#pragma unroll
            for (int nj = 0; nj < 2; nj++) {
                uint32_t bd = base + OBH
                            + (uint32_t)((brow + nj * 16) * GRS + kofs + bcol0) * 2;
                uint32_t t[4];
                ldsm4(t, bd);
                bh[nj*2][0] = t[0]; bh[nj*2][1] = t[1];
                bh[nj*2+1][0] = t[2]; bh[nj*2+1][1] = t[3];
            }
#pragma unroll
            for (int mi = 0; mi < 4; mi++)
#pragma unroll
                for (int ni = 0; ni < 4; ni++)
                    mma16816(acc[mi][ni], ah[mi], bh[ni]);
        }
    };

    do_issue(0, 0);
    for (int it = 0; it < NCH; it++) {
        asm volatile("cp.async.wait_group 0;");
        __syncthreads();
        if (it + 1 < NCH) do_issue(it + 1, (it + 1) & 1);
        do_compute(it & 1);
    }

    // ---- epilogue ----
#pragma unroll
    for (int mi = 0; mi < 4; mi++) {
        int row = m0 + wm + mi * 16 + (lane >> 2);
#pragma unroll
        for (int ni = 0; ni < 4; ni++) {
            int col = n0 + wn + ni * 8 + (lane & 3) * 2;
            float c0 = acc[mi][ni][0], c1 = acc[mi][ni][1];
            float c2 = acc[mi][ni][2], c3 = acc[mi][ni][3];
            if (act) {
                c0 = 1.f / (1.f + __expf(-c0));
                c1 = 1.f / (1.f + __expf(-c1));
                c2 = 1.f / (1.f + __expf(-c2));
                c3 = 1.f / (1.f + __expf(-c3));
            }
            if (o16) {
                __half* Ch = (__half*)args.C[z];
                *(uint32_t*)(Ch + (size_t)row * ND + col)       = packh(c0, c1);
                *(uint32_t*)(Ch + (size_t)(row + 8) * ND + col) = packh(c2, c3);
            } else {
                float* Cf = (float*)args.C[z];
                *(float2*)(Cf + (size_t)row * ND + col)       = make_float2(c0, c1);
                *(float2*)(Cf + (size_t)(row + 8) * ND + col) = make_float2(c2, c3);
            }
        }
    }
}

// ---------------------------------------------------------------------------
// 3a) WKV chunk aggregates — 128 threads = 4 warps, one chunk per warp
// ---------------------------------------------------------------------------
__global__ void __launch_bounds__(128)
wkv_chunk_agg(const __half* __restrict__ kArr,
              const __half* __restrict__ vArr,
              const float* __restrict__ td)
{
    const int bh = blockIdx.x;
    const int c  = blockIdx.y * 4 + (threadIdx.x >> 5);
    const int b = bh / NH;
    const int h = bh - b * NH;
    const int kk = threadIdx.x & 31;
    const int ch = h * NK + 2 * kk;

    const float w0 = __expf(-__expf(td[ch]));
    const float w1 = __expf(-__expf(td[ch + 1]));
    size_t base2 = ((size_t)b * NT * ND + (size_t)c * LL * ND + ch) >> 1;
    const __half2* k2 = (const __half2*)kArr;
    const __half2* v2 = (const __half2*)vArr;

    float N0 = 0.f, N1 = 0.f, D0 = 0.f, D1 = 0.f;
#pragma unroll 8
    for (int i = 0; i < LL; i++) {
        size_t idx = base2 + (size_t)i * (ND / 2);
        float2 kf = __half22float2(k2[idx]);
        float2 vf = __half22float2(v2[idx]);
        float e0 = __expf(kf.x), e1 = __expf(kf.y);
        N0 = fmaf(N0, w0, e0 * vf.x);
        D0 = fmaf(D0, w0, e0);
        N1 = fmaf(N1, w1, e1 * vf.y);
        D1 = fmaf(D1, w1, e1);
    }
    int o = (bh * CC + c) * NK + 2 * kk;
    g_Nloc[o]     = N0;  g_Nloc[o + 1] = N1;
    g_Dloc[o]     = D0;  g_Dloc[o + 1] = D1;
}

// ---------------------------------------------------------------------------
// 3b) scan across chunks
// ---------------------------------------------------------------------------
__global__ void __launch_bounds__(64)
wkv_chunk_scan(const float* __restrict__ td)
{
    const int bh = blockIdx.x;
    const int b = bh / NH;
    const int h = bh - b * NH;
    const int kk = threadIdx.x;
    const int ch = h * NK + kk;

    if (kk == 0) { g_s1[bh] = 0.f; g_s2[bh] = 0.f; }

    const float wL = __expf(-(float)LL * __expf(td[ch]));

    float cN = 0.f, cD = 0.f;
    for (int c = 0; c < CC; c++) {
        int o = (bh * CC + c) * NK + kk;
        g_InN[o] = cN;
        g_InD[o] = cD;
        cN = fmaf(cN, wL, g_Nloc[o]);
        cD = fmaf(cD, wL, g_Dloc[o]);
    }
}

// ---------------------------------------------------------------------------
// 3c) WKV outputs — 128 threads = 4 warps, one chunk per warp + GN sums
// ---------------------------------------------------------------------------
__global__ void __launch_bounds__(128)
wkv_out(const __half* __restrict__ kArr,
        const __half* __restrict__ vArr,
        const __half* __restrict__ rArr,
        const float* __restrict__ td,
        const float* __restrict__ tf,
        __half* __restrict__ y)
{
    const int bh = blockIdx.x;
    const int c  = blockIdx.y * 4 + (threadIdx.x >> 5);
    const int b = bh / NH;
    const int h = bh - b * NH;
    const int kk = threadIdx.x & 31;
    const int ch = h * NK + 2 * kk;

    const float w0  = __expf(-__expf(td[ch]));
    const float w1  = __expf(-__expf(td[ch + 1]));
    const float eu0 = __expf(tf[ch]);
    const float eu1 = __expf(tf[ch + 1]);
    size_t base2 = ((size_t)b * NT * ND + (size_t)c * LL * ND + ch) >> 1;
    const __half2* k2 = (const __half2*)kArr;
    const __half2* v2 = (const __half2*)vArr;
    const __half2* r2 = (const __half2*)rArr;
    __half2* y2 = (__half2*)y;

    int o = (bh * CC + c) * NK + 2 * kk;
    float num0 = g_InN[o], num1 = g_InN[o + 1];
    float den0 = g_InD[o], den1 = g_InD[o + 1];

    float s1 = 0.f, s2 = 0.f;
#pragma unroll 4
    for (int i = 0; i < LL; i++) {
        size_t idx = base2 + (size_t)i * (ND / 2);
        float2 kf = __half22float2(k2[idx]);
        float2 vf = __half22float2(v2[idx]);
        float2 rf = __half22float2(r2[idx]);
        float e0 = __expf(kf.x), e1 = __expf(kf.y);
        float ekv0 = e0 * vf.x, ekv1 = e1 * vf.y;
        float yy0 = rf.x * __fdividef(fmaf(eu0, ekv0, num0),
                                      fmaf(eu0, e0, den0) + 1e-9f);
        float yy1 = rf.y * __fdividef(fmaf(eu1, ekv1, num1),
                                      fmaf(eu1, e1, den1) + 1e-9f);
        y2[idx] = __floats2half2_rn(yy0, yy1);
        s1 += yy0 + yy1;
        s2 = fmaf(yy0, yy0, s2);
        s2 = fmaf(yy1, yy1, s2);
        num0 = fmaf(num0, w0, ekv0);
        den0 = fmaf(den0, w0, e0);
        num1 = fmaf(num1, w1, ekv1);
        den1 = fmaf(den1, w1, e1);
    }

#pragma unroll
    for (int off = 16; off > 0; off >>= 1) {
        s1 += __shfl_down_sync(0xffffffffu, s1, off);
        s2 += __shfl_down_sync(0xffffffffu, s2, off);
    }
    if (kk == 0) {
        atomicAdd(&g_s1[bh], s1);
        atomicAdd(&g_s2[bh], s2);
    }
}

// ---------------------------------------------------------------------------
// 4) GroupNorm apply: fp16 y in -> fp16 yn out (into g_xrh)
// ---------------------------------------------------------------------------
__global__ void norm_f16(const float* __restrict__ gnw,
                         const float* __restrict__ gnb)
{
    size_t idx = (size_t)blockIdx.x * blockDim.x + threadIdx.x;
    const size_t n8 = (size_t)NM * ND / 8;
    if (idx >= n8) return;
    size_t e = idx * 8;
    int d = (int)(e % ND);
    int b = (int)(e / ((size_t)NT * ND));
    int h = d >> 6;
    int bh = b * NH + h;

    const float inv = 1.f / (float)(NT * NK);
    float mean = g_s1[bh] * inv;
    float var  = g_s2[bh] * inv - mean * mean;
    float rstd = rsqrtf(var + 1e-5f);

    uint4 raw = ((const uint4*)g_y16)[idx];
    float yv[8];
    {
        __half2 p0 = *(__half2*)&raw.x;
        __half2 p1 = *(__half2*)&raw.y;
        __half2 p2 = *(__half2*)&raw.z;
        __half2 p3 = *(__half2*)&raw.w;
        float2 f0 = __half22float2(p0), f1 = __half22float2(p1);
        float2 f2 = __half22float2(p2), f3 = __half22float2(p3);
        yv[0]=f0.x; yv[1]=f0.y; yv[2]=f1.x; yv[3]=f1.y;
        yv[4]=f2.x; yv[5]=f2.y; yv[6]=f3.x; yv[7]=f3.y;
    }
    float4 w0 = ((const float4*)gnw)[d>>2], w1 = ((const float4*)gnw)[(d>>2)+1];
    float4 b0 = ((const float4*)gnb)[d>>2], b1 = ((const float4*)gnb)[(d>>2)+1];
    float wv[8] = {w0.x,w0.y,w0.z,w0.w,w1.x,w1.y,w1.z,w1.w};
    float bv[8] = {b0.x,b0.y,b0.z,b0.w,b1.x,b1.y,b1.z,b1.w};
    float m[8];
#pragma unroll
    for (int i = 0; i < 8; i++)
        m[i] = (yv[i] - mean) * rstd * wv[i] + bv[i];

    ((uint4*)g_xrh)[idx] = pack8h(m);
}

// ---------------------------------------------------------------------------
// host launcher — single-stream, proven-best schedule
// ---------------------------------------------------------------------------
extern "C" void kernel_launch(void* const* d_in, const int* in_sizes, int n_in,
                              void* d_out, int out_size)
{
    const float* x   = (const float*)d_in[0];
    const float* tmr = (const float*)d_in[1];
    const float* tmk = (const float*)d_in[2];
    const float* tmv = (const float*)d_in[3];
    const float* td  = (const float*)d_in[4];
    const float* tf  = (const float*)d_in[5];
    const float* Wr  = (const float*)d_in[6];
    const float* Wk  = (const float*)d_in[7];
    const float* Wv  = (const float*)d_in[8];
    const float* Wo  = (const float*)d_in[9];
    const float* gnw = (const float*)d_in[10];
    const float* gnb = (const float*)d_in[11];
    float* out = (float*)d_out;

    __half *xrh, *xkh, *xvh, *k16, *v16, *r16, *y16, *wh;
    cudaGetSymbolAddress((void**)&xrh, g_xrh);
    cudaGetSymbolAddress((void**)&xkh, g_xkh);
    cudaGetSymbolAddress((void**)&xvh, g_xvh);
    cudaGetSymbolAddress((void**)&k16, g_k16);
    cudaGetSymbolAddress((void**)&v16, g_v16);
    cudaGetSymbolAddress((void**)&r16, g_r16);
    cudaGetSymbolAddress((void**)&y16, g_y16);
    cudaGetSymbolAddress((void**)&wh, g_Wh);

    cudaFuncSetAttribute((const void*)gemm_mma_batched,
                         cudaFuncAttributeMaxDynamicSharedMemorySize,
                         GEMM_SMEM_BYTES);

    const size_t n8 = (size_t)NM * ND / 8;
    const int blk = 256;
    const int grd8 = (int)((n8 + blk - 1) / blk);

    // fused weight converts + token-shift mix (one launch)
    dim3 pgrid(grd8, 5);
    prep_all<<<pgrid, blk>>>(x, tmr, tmk, tmv, Wr, Wk, Wv, Wo, wh);

    // fused r/k/v projections (single batched launch)
    GemmArgs qkv;
    qkv.A[0] = xrh; qkv.B[0] = wh + 0*(size_t)ND*ND; qkv.C[0] = r16;  // r (sigmoid)
    qkv.A[1] = xkh; qkv.B[1] = wh + 1*(size_t)ND*ND; qkv.C[1] = k16;  // k
    qkv.A[2] = xvh; qkv.B[2] = wh + 2*(size_t)ND*ND; qkv.C[2] = v16;  // v
    qkv.actmask = 1;
    qkv.f16mask = 7;
    dim3 ggrid(ND / BN, NM / BM, 3);   // (6, 256, 3)
    gemm_mma_batched<<<ggrid, 256, GEMM_SMEM_BYTES>>>(qkv);

    // chunked parallel WKV scan: y -> y16
    dim3 wgrid(NB * NH, CC / 4);
    wkv_chunk_agg <<<wgrid, 128>>>(k16, v16, td);
    wkv_chunk_scan<<<NB * NH, 64>>>(td);
    wkv_out       <<<wgrid, 128>>>(k16, v16, r16, td, tf, y16);

    // GroupNorm apply -> fp16 yn (into xrh)
    norm_f16<<<grd8, blk>>>(gnw, gnb);

    // output projection (fp32 into d_out)
    GemmArgs og;
    og.A[0] = xrh; og.B[0] = wh + 3*(size_t)ND*ND; og.C[0] = out;
    og.A[1] = og.A[2] = xrh;
    og.B[1] = og.B[2] = og.B[0];
    og.C[1] = og.C[2] = out;
    og.actmask = 0;
    og.f16mask = 0;
    dim3 ogrid(ND / BN, NM / BM, 1);
    gemm_mma_batched<<<ogrid, 256, GEMM_SMEM_BYTES>>>(og);
}

// round 16
// speedup vs baseline: 1.1630x; 1.0632x over previous
#include <cuda_runtime.h>
#include <cuda_fp16.h>
#include <math.h>
#include <stdint.h>

// Problem dims (fixed)
#define NB 8
#define NT 4096
#define ND 768
#define NH 12
#define NK 64
#define NM (NB*NT)          // 32768 rows
#define CC 64               // chunks along T (wkv scan)
#define LL 64               // chunk length

// GEMM tiling: BM=BN=128, 256 threads, 2 CTAs/SM, GBK=64, fp16, 2-stage
// (empirically optimal across rounds 9-15; frozen)
#define BM 128
#define BN 128
#define GBK 64
#define NCH (ND/GBK)        // 12 k-iterations
#define GRS 72              // smem row stride in fp16 elems (144B)
#define SUBB (128*GRS*2)    // bytes per subtile (18432)
#define OAH 0
#define OBH SUBB
#define STGB (2*SUBB)       // 36864 B per stage
#define GEMM_SMEM_BYTES (2*STGB)    // 73728 B

// ---------------------------------------------------------------------------
// Scratch buffers (all intermediates fp16)
// ---------------------------------------------------------------------------
__device__ __half g_xrh[(size_t)NM * ND];   // xr -> (after norm) yn
__device__ __half g_xkh[(size_t)NM * ND];   // xk
__device__ __half g_xvh[(size_t)NM * ND];   // xv
__device__ __half g_k16[(size_t)NM * ND];   // k
__device__ __half g_v16[(size_t)NM * ND];   // v
__device__ __half g_r16[(size_t)NM * ND];   // r
__device__ __half g_y16[(size_t)NM * ND];   // y (pre-norm)
__device__ __half g_Wh[4][ND * ND];         // fp16 weights

// wkv chunked-scan intermediates
__device__ float g_Nloc[NB * NH * CC * NK];
__device__ float g_Dloc[NB * NH * CC * NK];
__device__ float g_InN [NB * NH * CC * NK];
__device__ float g_InD [NB * NH * CC * NK];
__device__ float g_s1[NB * NH];
__device__ float g_s2[NB * NH];

// ---------------------------------------------------------------------------
// helpers
// ---------------------------------------------------------------------------
__device__ __forceinline__ uint32_t smem_u32(const void* p) {
    uint32_t a;
    asm("{ .reg .u64 t; cvta.to.shared.u64 t, %1; cvt.u32.u64 %0, t; }"
        : "=r"(a) : "l"(p));
    return a;
}

__device__ __forceinline__ uint32_t packh(float a, float b) {
    uint32_t r;
    asm("cvt.rn.f16x2.f32 %0, %1, %2;" : "=r"(r) : "f"(b), "f"(a));
    return r;
}

__device__ __forceinline__ uint4 pack8h(const float* m) {
    uint4 r;
    r.x = packh(m[0], m[1]);
    r.y = packh(m[2], m[3]);
    r.z = packh(m[4], m[5]);
    r.w = packh(m[6], m[7]);
    return r;
}

__device__ __forceinline__ void ldsm4(uint32_t* r, uint32_t addr) {
    asm volatile("ldmatrix.sync.aligned.m8n8.x4.shared.b16 {%0,%1,%2,%3}, [%4];"
                 : "=r"(r[0]), "=r"(r[1]), "=r"(r[2]), "=r"(r[3]) : "r"(addr));
}

__device__ __forceinline__ void mma16816(float* c, const uint32_t* a, const uint32_t* b) {
    asm volatile(
        "mma.sync.aligned.m16n8k16.row.col.f32.f16.f16.f32 "
        "{%0,%1,%2,%3}, {%4,%5,%6,%7}, {%8,%9}, {%0,%1,%2,%3};"
        : "+f"(c[0]), "+f"(c[1]), "+f"(c[2]), "+f"(c[3])
        : "r"(a[0]), "r"(a[1]), "r"(a[2]), "r"(a[3]), "r"(b[0]), "r"(b[1]));
}

__device__ __forceinline__ void cpasync16(uint32_t saddr, const void* gptr) {
    asm volatile("cp.async.cg.shared.global [%0], [%1], 16;"
                 :: "r"(saddr), "l"(__cvta_generic_to_global(gptr)));
}

// ---------------------------------------------------------------------------
// fused weight convert (grid.y = 4): fp32 W -> fp16
// ---------------------------------------------------------------------------
__global__ void split_all(const float* __restrict__ W0, const float* __restrict__ W1,
                          const float* __restrict__ W2, const float* __restrict__ W3,
                          __half* __restrict__ whbase)
{
    const int z = blockIdx.y;
    const float* src = (z == 0) ? W0 : (z == 1) ? W1 : (z == 2) ? W2 : W3;
    __half* h = whbase + (size_t)z * ND * ND;
    const int n8 = ND * ND / 8;
    int idx = blockIdx.x * blockDim.x + threadIdx.x;
    if (idx >= n8) return;
    const float4* s4 = (const float4*)src;
    float4 a0 = s4[idx*2], a1 = s4[idx*2+1];
    float m[8] = {a0.x,a0.y,a0.z,a0.w,a1.x,a1.y,a1.z,a1.w};
    ((uint4*)h)[idx] = pack8h(m);
}

// ---------------------------------------------------------------------------
// 1) Token-shift mixing, fp16 output
// ---------------------------------------------------------------------------
__global__ void mix_f16(const float* __restrict__ x,
                        const float* __restrict__ tmr,
                        const float* __restrict__ tmk,
                        const float* __restrict__ tmv)
{
    size_t idx = (size_t)blockIdx.x * blockDim.x + threadIdx.x;
    const size_t n8 = (size_t)NM * ND / 8;
    if (idx >= n8) return;
    size_t e = idx * 8;
    int d = (int)(e % ND);
    int t = (int)((e / ND) % NT);

    const float4* x4 = (const float4*)x;
    float4 a0 = x4[idx*2], a1 = x4[idx*2+1];
    float4 p0 = make_float4(0.f,0.f,0.f,0.f), p1 = p0;
    if (t != 0) { p0 = x4[idx*2 - ND/4]; p1 = x4[idx*2 + 1 - ND/4]; }

    float xc[8] = {a0.x,a0.y,a0.z,a0.w,a1.x,a1.y,a1.z,a1.w};
    float xp[8] = {p0.x,p0.y,p0.z,p0.w,p1.x,p1.y,p1.z,p1.w};

    float mr[8], mk[8], mv[8];
    {
        float4 r0 = ((const float4*)tmr)[d>>2], r1 = ((const float4*)tmr)[(d>>2)+1];
        float4 k0 = ((const float4*)tmk)[d>>2], k1 = ((const float4*)tmk)[(d>>2)+1];
        float4 v0 = ((const float4*)tmv)[d>>2], v1 = ((const float4*)tmv)[(d>>2)+1];
        float mrr[8] = {r0.x,r0.y,r0.z,r0.w,r1.x,r1.y,r1.z,r1.w};
        float mkk[8] = {k0.x,k0.y,k0.z,k0.w,k1.x,k1.y,k1.z,k1.w};
        float mvv[8] = {v0.x,v0.y,v0.z,v0.w,v1.x,v1.y,v1.z,v1.w};
#pragma unroll
        for (int i = 0; i < 8; i++) {
            float dx = xc[i] - xp[i];
            mr[i] = fmaf(dx, mrr[i], xp[i]);
            mk[i] = fmaf(dx, mkk[i], xp[i]);
            mv[i] = fmaf(dx, mvv[i], xp[i]);
        }
    }
    ((uint4*)g_xrh)[idx] = pack8h(mr);
    ((uint4*)g_xkh)[idx] = pack8h(mk);
    ((uint4*)g_xvh)[idx] = pack8h(mv);
}

// ---------------------------------------------------------------------------
// 2) Batched tensor-core GEMM, pure fp16: C = A*Wh  (2-stage, 2 CTAs/SM)
// ---------------------------------------------------------------------------
struct GemmArgs {
    const __half* A[3];
    const __half* B[3];
    void* C[3];
    int actmask;   // bit z: apply sigmoid
    int f16mask;   // bit z: output fp16
};

__global__ void __launch_bounds__(256, 2)
gemm_mma_batched(GemmArgs args)
{
    extern __shared__ __half smraw[];
    const uint32_t sb = smem_u32(smraw);
    const int tid  = threadIdx.x;
    const int lane = tid & 31;
    const int wid  = tid >> 5;
    const int z  = blockIdx.z;
    const int m0 = blockIdx.y * BM;
    const int n0 = blockIdx.x * BN;
    const int wm = (wid >> 2) * 64;
    const int wn = (wid & 3) * 32;

    const __half* __restrict__ A = args.A[z];
    const __half* __restrict__ B = args.B[z];
    const bool act = (args.actmask >> z) & 1;
    const bool o16 = (args.f16mask >> z) & 1;

    float acc[4][4][4];
#pragma unroll
    for (int i = 0; i < 4; i++)
#pragma unroll
        for (int j = 0; j < 4; j++)
#pragma unroll
            for (int q = 0; q < 4; q++) acc[i][j][q] = 0.f;

    auto do_issue = [&](int it, int stg) {
        const int kt = it * GBK;
        const uint32_t sbase = sb + (uint32_t)stg * STGB;
#pragma unroll
        for (int j = 0; j < 4; j++) {
            int g   = tid + j * 256;       // 0..1023
            int row = g >> 3;              // 0..127
            int kc  = (g & 7) * 8;         // 0..56
            uint32_t so = (uint32_t)(row * GRS + kc) * 2;
            size_t ga = (size_t)(m0 + row) * ND + kt + kc;
            size_t gb = (size_t)(n0 + row) * ND + kt + kc;
            cpasync16(sbase + OAH + so, A + ga);
            cpasync16(sbase + OBH + so, B + gb);
        }
        asm volatile("cp.async.commit_group;");
    };

    auto do_compute = [&](int stg) {
        const uint32_t base = sb + (uint32_t)stg * STGB;
        const int arow = wm + (lane & 15);
        const int acol0 = (lane >> 4) * 8;
        const int brow = wn + ((lane >> 4) << 3) + (lane & 7);
        const int bcol0 = ((lane >> 3) & 1) * 8;
#pragma unroll
        for (int ks = 0; ks < 4; ks++) {
            uint32_t ah[4][4], bh[4][2];
            const int kofs = ks * 16;
#pragma unroll
            for (int mi = 0; mi < 4; mi++) {
                uint32_t ad = base + OAH
                            + (uint32_t)((arow + mi * 16) * GRS + kofs + acol0) * 2;
                ldsm4(ah[mi], ad);
            }
#pragma unroll
            for (int nj = 0; nj < 2; nj++) {
                uint32_t bd = base + OBH
                            + (uint32_t)((brow + nj * 16) * GRS + kofs + bcol0) * 2;
                uint32_t t[4];
                ldsm4(t, bd);
                bh[nj*2][0] = t[0]; bh[nj*2][1] = t[1];
                bh[nj*2+1][0] = t[2]; bh[nj*2+1][1] = t[3];
            }
#pragma unroll
            for (int mi = 0; mi < 4; mi++)
#pragma unroll
                for (int ni = 0; ni < 4; ni++)
                    mma16816(acc[mi][ni], ah[mi], bh[ni]);
        }
    };

    do_issue(0, 0);
    for (int it = 0; it < NCH; it++) {
        asm volatile("cp.async.wait_group 0;");
        __syncthreads();
        if (it + 1 < NCH) do_issue(it + 1, (it + 1) & 1);
        do_compute(it & 1);
    }

    // ---- epilogue ----
#pragma unroll
    for (int mi = 0; mi < 4; mi++) {
        int row = m0 + wm + mi * 16 + (lane >> 2);
#pragma unroll
        for (int ni = 0; ni < 4; ni++) {
            int col = n0 + wn + ni * 8 + (lane & 3) * 2;
            float c0 = acc[mi][ni][0], c1 = acc[mi][ni][1];
            float c2 = acc[mi][ni][2], c3 = acc[mi][ni][3];
            if (act) {
                c0 = 1.f / (1.f + __expf(-c0));
                c1 = 1.f / (1.f + __expf(-c1));
                c2 = 1.f / (1.f + __expf(-c2));
                c3 = 1.f / (1.f + __expf(-c3));
            }
            if (o16) {
                __half* Ch = (__half*)args.C[z];
                *(uint32_t*)(Ch + (size_t)row * ND + col)       = packh(c0, c1);
                *(uint32_t*)(Ch + (size_t)(row + 8) * ND + col) = packh(c2, c3);
            } else {
                float* Cf = (float*)args.C[z];
                *(float2*)(Cf + (size_t)row * ND + col)       = make_float2(c0, c1);
                *(float2*)(Cf + (size_t)(row + 8) * ND + col) = make_float2(c2, c3);
            }
        }
    }
}

// ---------------------------------------------------------------------------
// 3a) WKV chunk aggregates — 128 threads = 4 warps, one chunk per warp
// ---------------------------------------------------------------------------
__global__ void __launch_bounds__(128)
wkv_chunk_agg(const __half* __restrict__ kArr,
              const __half* __restrict__ vArr,
              const float* __restrict__ td)
{
    const int bh = blockIdx.x;
    const int c  = blockIdx.y * 4 + (threadIdx.x >> 5);
    const int b = bh / NH;
    const int h = bh - b * NH;
    const int kk = threadIdx.x & 31;
    const int ch = h * NK + 2 * kk;

    const float w0 = __expf(-__expf(td[ch]));
    const float w1 = __expf(-__expf(td[ch + 1]));
    size_t base2 = ((size_t)b * NT * ND + (size_t)c * LL * ND + ch) >> 1;
    const __half2* k2 = (const __half2*)kArr;
    const __half2* v2 = (const __half2*)vArr;

    float N0 = 0.f, N1 = 0.f, D0 = 0.f, D1 = 0.f;
#pragma unroll 8
    for (int i = 0; i < LL; i++) {
        size_t idx = base2 + (size_t)i * (ND / 2);
        float2 kf = __half22float2(k2[idx]);
        float2 vf = __half22float2(v2[idx]);
        float e0 = __expf(kf.x), e1 = __expf(kf.y);
        N0 = fmaf(N0, w0, e0 * vf.x);
        D0 = fmaf(D0, w0, e0);
        N1 = fmaf(N1, w1, e1 * vf.y);
        D1 = fmaf(D1, w1, e1);
    }
    int o = (bh * CC + c) * NK + 2 * kk;
    g_Nloc[o]     = N0;  g_Nloc[o + 1] = N1;
    g_Dloc[o]     = D0;  g_Dloc[o + 1] = D1;
}

// ---------------------------------------------------------------------------
// 3b) scan across chunks — smem-staged (one block per bh, 256 threads)
//     Phase 1: coalesced bulk load of Nloc/Dloc -> smem (high MLP)
//     Phase 2: 64 threads scan their channel in smem (29cyc LDS vs 600 LDG)
//     Phase 3: coalesced store of incoming states
// ---------------------------------------------------------------------------
__global__ void __launch_bounds__(256)
wkv_chunk_scan(const float* __restrict__ td)
{
    __shared__ float sN[CC * NK];   // 16 KB
    __shared__ float sD[CC * NK];   // 16 KB
    const int bh = blockIdx.x;
    const int b = bh / NH;
    const int h = bh - b * NH;
    const int tid = threadIdx.x;
    const int base = bh * CC * NK;

    if (tid == 0) { g_s1[bh] = 0.f; g_s2[bh] = 0.f; }

    // phase 1: bulk load (float4, coalesced, 4 elems/thread/iter)
    const float4* gN4 = (const float4*)(g_Nloc + base);
    const float4* gD4 = (const float4*)(g_Dloc + base);
    float4* sN4 = (float4*)sN;
    float4* sD4 = (float4*)sD;
#pragma unroll
    for (int i = 0; i < CC * NK / 4 / 256; i++) {   // 4 iters
        int j = tid + i * 256;
        sN4[j] = gN4[j];
        sD4[j] = gD4[j];
    }
    __syncthreads();

    // phase 2: per-channel scan in smem (in-place: overwrite with incoming state)
    if (tid < NK) {
        const int kk = tid;
        const float wL = __expf(-(float)LL * __expf(td[h * NK + kk]));
        float cN = 0.f, cD = 0.f;
#pragma unroll 4
        for (int c = 0; c < CC; c++) {
            int o = c * NK + kk;
            float n = sN[o], d = sD[o];
            sN[o] = cN;
            sD[o] = cD;
            cN = fmaf(cN, wL, n);
            cD = fmaf(cD, wL, d);
        }
    }
    __syncthreads();

    // phase 3: bulk store
    float4* iN4 = (float4*)(g_InN + base);
    float4* iD4 = (float4*)(g_InD + base);
#pragma unroll
    for (int i = 0; i < CC * NK / 4 / 256; i++) {
        int j = tid + i * 256;
        iN4[j] = sN4[j];
        iD4[j] = sD4[j];
    }
}

// ---------------------------------------------------------------------------
// 3c) WKV outputs — 128 threads = 4 warps, one chunk per warp + GN sums
// ---------------------------------------------------------------------------
__global__ void __launch_bounds__(128)
wkv_out(const __half* __restrict__ kArr,
        const __half* __restrict__ vArr,
        const __half* __restrict__ rArr,
        const float* __restrict__ td,
        const float* __restrict__ tf,
        __half* __restrict__ y)
{
    const int bh = blockIdx.x;
    const int c  = blockIdx.y * 4 + (threadIdx.x >> 5);
    const int b = bh / NH;
    const int h = bh - b * NH;
    const int kk = threadIdx.x & 31;
    const int ch = h * NK + 2 * kk;

    const float w0  = __expf(-__expf(td[ch]));
    const float w1  = __expf(-__expf(td[ch + 1]));
    const float eu0 = __expf(tf[ch]);
    const float eu1 = __expf(tf[ch + 1]);
    size_t base2 = ((size_t)b * NT * ND + (size_t)c * LL * ND + ch) >> 1;
    const __half2* k2 = (const __half2*)kArr;
    const __half2* v2 = (const __half2*)vArr;
    const __half2* r2 = (const __half2*)rArr;
    __half2* y2 = (__half2*)y;

    int o = (bh * CC + c) * NK + 2 * kk;
    float num0 = g_InN[o], num1 = g_InN[o + 1];
    float den0 = g_InD[o], den1 = g_InD[o + 1];

    float s1 = 0.f, s2 = 0.f;
#pragma unroll 4
    for (int i = 0; i < LL; i++) {
        size_t idx = base2 + (size_t)i * (ND / 2);
        float2 kf = __half22float2(k2[idx]);
        float2 vf = __half22float2(v2[idx]);
        float2 rf = __half22float2(r2[idx]);
        float e0 = __expf(kf.x), e1 = __expf(kf.y);
        float ekv0 = e0 * vf.x, ekv1 = e1 * vf.y;
        float yy0 = rf.x * __fdividef(fmaf(eu0, ekv0, num0),
                                      fmaf(eu0, e0, den0) + 1e-9f);
        float yy1 = rf.y * __fdividef(fmaf(eu1, ekv1, num1),
                                      fmaf(eu1, e1, den1) + 1e-9f);
        y2[idx] = __floats2half2_rn(yy0, yy1);
        s1 += yy0 + yy1;
        s2 = fmaf(yy0, yy0, s2);
        s2 = fmaf(yy1, yy1, s2);
        num0 = fmaf(num0, w0, ekv0);
        den0 = fmaf(den0, w0, e0);
        num1 = fmaf(num1, w1, ekv1);
        den1 = fmaf(den1, w1, e1);
    }

#pragma unroll
    for (int off = 16; off > 0; off >>= 1) {
        s1 += __shfl_down_sync(0xffffffffu, s1, off);
        s2 += __shfl_down_sync(0xffffffffu, s2, off);
    }
    if (kk == 0) {
        atomicAdd(&g_s1[bh], s1);
        atomicAdd(&g_s2[bh], s2);
    }
}

// ---------------------------------------------------------------------------
// 4) GroupNorm apply: fp16 y in -> fp16 yn out (into g_xrh)
// ---------------------------------------------------------------------------
__global__ void norm_f16(const float* __restrict__ gnw,
                         const float* __restrict__ gnb)
{
    size_t idx = (size_t)blockIdx.x * blockDim.x + threadIdx.x;
    const size_t n8 = (size_t)NM * ND / 8;
    if (idx >= n8) return;
    size_t e = idx * 8;
    int d = (int)(e % ND);
    int b = (int)(e / ((size_t)NT * ND));
    int h = d >> 6;
    int bh = b * NH + h;

    const float inv = 1.f / (float)(NT * NK);
    float mean = g_s1[bh] * inv;
    float var  = g_s2[bh] * inv - mean * mean;
    float rstd = rsqrtf(var + 1e-5f);

    uint4 raw = ((const uint4*)g_y16)[idx];
    float yv[8];
    {
        __half2 p0 = *(__half2*)&raw.x;
        __half2 p1 = *(__half2*)&raw.y;
        __half2 p2 = *(__half2*)&raw.z;
        __half2 p3 = *(__half2*)&raw.w;
        float2 f0 = __half22float2(p0), f1 = __half22float2(p1);
        float2 f2 = __half22float2(p2), f3 = __half22float2(p3);
        yv[0]=f0.x; yv[1]=f0.y; yv[2]=f1.x; yv[3]=f1.y;
        yv[4]=f2.x; yv[5]=f2.y; yv[6]=f3.x; yv[7]=f3.y;
    }
    float4 w0 = ((const float4*)gnw)[d>>2], w1 = ((const float4*)gnw)[(d>>2)+1];
    float4 b0 = ((const float4*)gnb)[d>>2], b1 = ((const float4*)gnb)[(d>>2)+1];
    float wv[8] = {w0.x,w0.y,w0.z,w0.w,w1.x,w1.y,w1.z,w1.w};
    float bv[8] = {b0.x,b0.y,b0.z,b0.w,b1.x,b1.y,b1.z,b1.w};
    float m[8];
#pragma unroll
    for (int i = 0; i < 8; i++)
        m[i] = (yv[i] - mean) * rstd * wv[i] + bv[i];

    ((uint4*)g_xrh)[idx] = pack8h(m);
}

// ---------------------------------------------------------------------------
// host launcher — single-stream, proven-best schedule
// ---------------------------------------------------------------------------
extern "C" void kernel_launch(void* const* d_in, const int* in_sizes, int n_in,
                              void* d_out, int out_size)
{
    const float* x   = (const float*)d_in[0];
    const float* tmr = (const float*)d_in[1];
    const float* tmk = (const float*)d_in[2];
    const float* tmv = (const float*)d_in[3];
    const float* td  = (const float*)d_in[4];
    const float* tf  = (const float*)d_in[5];
    const float* Wr  = (const float*)d_in[6];
    const float* Wk  = (const float*)d_in[7];
    const float* Wv  = (const float*)d_in[8];
    const float* Wo  = (const float*)d_in[9];
    const float* gnw = (const float*)d_in[10];
    const float* gnb = (const float*)d_in[11];
    float* out = (float*)d_out;

    __half *xrh, *xkh, *xvh, *k16, *v16, *r16, *y16, *wh;
    cudaGetSymbolAddress((void**)&xrh, g_xrh);
    cudaGetSymbolAddress((void**)&xkh, g_xkh);
    cudaGetSymbolAddress((void**)&xvh, g_xvh);
    cudaGetSymbolAddress((void**)&k16, g_k16);
    cudaGetSymbolAddress((void**)&v16, g_v16);
    cudaGetSymbolAddress((void**)&r16, g_r16);
    cudaGetSymbolAddress((void**)&y16, g_y16);
    cudaGetSymbolAddress((void**)&wh, g_Wh);

    cudaFuncSetAttribute((const void*)gemm_mma_batched,
                         cudaFuncAttributeMaxDynamicSharedMemorySize,
                         GEMM_SMEM_BYTES);

    const size_t n8 = (size_t)NM * ND / 8;
    const int blk = 256;
    const int grd8 = (int)((n8 + blk - 1) / blk);
    const int wn8 = ND * ND / 8;
    const int wgrd = (wn8 + blk - 1) / blk;

    // weight converts + mix (correct grids)
    dim3 sgrid(wgrd, 4);
    split_all<<<sgrid, blk>>>(Wr, Wk, Wv, Wo, wh);
    mix_f16<<<grd8, blk>>>(x, tmr, tmk, tmv);

    // fused r/k/v projections (single batched launch)
    GemmArgs qkv;
    qkv.A[0] = xrh; qkv.B[0] = wh + 0*(size_t)ND*ND; qkv.C[0] = r16;  // r (sigmoid)
    qkv.A[1] = xkh; qkv.B[1] = wh + 1*(size_t)ND*ND; qkv.C[1] = k16;  // k
    qkv.A[2] = xvh; qkv.B[2] = wh + 2*(size_t)ND*ND; qkv.C[2] = v16;  // v
    qkv.actmask = 1;
    qkv.f16mask = 7;
    dim3 ggrid(ND / BN, NM / BM, 3);   // (6, 256, 3)
    gemm_mma_batched<<<ggrid, 256, GEMM_SMEM_BYTES>>>(qkv);

    // chunked parallel WKV scan: y -> y16
    dim3 wgrid(NB * NH, CC / 4);
    wkv_chunk_agg <<<wgrid, 128>>>(k16, v16, td);
    wkv_chunk_scan<<<NB * NH, 256>>>(td);
    wkv_out       <<<wgrid, 128>>>(k16, v16, r16, td, tf, y16);

    // GroupNorm apply -> fp16 yn (into xrh)
    norm_f16<<<grd8, blk>>>(gnw, gnb);

    // output projection (fp32 into d_out)
    GemmArgs og;
    og.A[0] = xrh; og.B[0] = wh + 3*(size_t)ND*ND; og.C[0] = out;
    og.A[1] = og.A[2] = xrh;
    og.B[1] = og.B[2] = og.B[0];
    og.C[1] = og.C[2] = out;
    og.actmask = 0;
    og.f16mask = 0;
    dim3 ogrid(ND / BN, NM / BM, 1);
    gemm_mma_batched<<<ogrid, 256, GEMM_SMEM_BYTES>>>(og);
}